// round 14
// baseline (speedup 1.0000x reference)
#include <cuda_runtime.h>
#include <cuda_pipeline.h>
#include <math.h>

#define RR 4
#define NN 4096
#define EE 2048
#define FF 128
#define HDIM 256
#define EW (EE/32)
#define NW (NN/32)
#define PART_S4 (RR*NN*64)

// ---------------- device scratch ----------------
__device__ float    g_rw[RR];
__device__ float    g_sig[3][RR];
__device__ float    g_dv[RR*NN];
__device__ float    g_cE[RR*EE];
__device__ unsigned g_maskN[(size_t)RR*NN*EW];
__device__ unsigned g_maskE[(size_t)RR*EE*NW];
__device__ float4   g_Xs [(size_t)RR*NN*64];
__device__ float4   g_T  [(size_t)RR*EE*64];
__device__ float4   g_Hn [(size_t)RR*NN*64];
__device__ float4   g_pre[(size_t)NN*64];
__device__ float4   g_part[(size_t)4*PART_S4];
__device__ float    g_bnp[2][16][HDIM];

// ---------------- prep ----------------
__global__ void prep_kernel(const float* __restrict__ rel, const float* __restrict__ imp) {
    if (threadIdx.x == 0) {
        float m = -1e30f;
        for (int r = 0; r < RR; r++) m = fmaxf(m, rel[r]);
        float e[RR], s = 0.f;
        for (int r = 0; r < RR; r++) { e[r] = expf(rel[r] - m); s += e[r]; }
        for (int r = 0; r < RR; r++) g_rw[r] = e[r] / s;
        for (int l = 0; l < 3; l++)
            for (int r = 0; r < RR; r++)
                g_sig[l][r] = 1.f / (1.f + expf(-imp[l*RR + r]));
    }
}

// ---------------- bitmask build ----------------
__global__ void build_maskN_kernel(const float* __restrict__ H) {
    int gw   = blockIdx.x * (blockDim.x >> 5) + (threadIdx.x >> 5);
    int lane = threadIdx.x & 31;
    if (gw >= RR*NN) return;
    int r = gw / NN;
    const float* row = H + (size_t)gw * EE;
    unsigned w0 = 0, w1 = 0;
    int cnt = 0;
    #pragma unroll 8
    for (int k = 0; k < 64; k++) {
        float v = row[k*32 + lane];
        unsigned b = __ballot_sync(0xffffffffu, v != 0.0f);
        cnt += (v != 0.0f) ? 1 : 0;
        if (k == lane)      w0 = b;
        if (k == lane + 32) w1 = b;
    }
    g_maskN[(size_t)gw*EW + lane]      = w0;
    g_maskN[(size_t)gw*EW + 32 + lane] = w1;
    int tot = __reduce_add_sync(0xffffffffu, cnt);
    if (lane == 0)
        g_dv[gw] = 1.0f / sqrtf(g_rw[r] * (float)tot + 1e-8f);
}

// ---------------- 32x32 bit transpose ----------------
__global__ void transpose_mask_kernel() {
    const int tilesPerR = (NN/32)*(EE/32);
    int gw   = blockIdx.x * (blockDim.x >> 5) + (threadIdx.x >> 5);
    int lane = threadIdx.x & 31;
    if (gw >= RR * tilesPerR) return;
    int r   = gw / tilesPerR;
    int rem = gw % tilesPerR;
    int nb  = rem / (EE/32);
    int eb  = rem % (EE/32);
    unsigned w = g_maskN[((size_t)r*NN + nb*32 + lane)*EW + eb];
    unsigned out = 0;
    #pragma unroll
    for (int j = 0; j < 32; j++) {
        unsigned b = __ballot_sync(0xffffffffu, (w >> j) & 1u);
        if (lane == j) out = b;
    }
    g_maskE[((size_t)r*EE + eb*32 + lane)*NW + nb] = out;
}

// ---------------- edge constants ----------------
__global__ void build_cE_kernel() {
    int gw   = blockIdx.x * (blockDim.x >> 5) + (threadIdx.x >> 5);
    int lane = threadIdx.x & 31;
    if (gw >= RR*EE) return;
    int r = gw / EE;
    const unsigned* row = g_maskE + (size_t)gw * NW;
    int cnt = 0;
    for (int k = lane; k < NW; k += 32) cnt += __popc(row[k]);
    cnt = __reduce_add_sync(0xffffffffu, cnt);
    if (lane == 0) {
        float rw = g_rw[r];
        g_cE[gw] = rw * rw / (rw * (float)cnt + 1e-8f);
    }
}

// ---------------- pre-scale source by dv (layer 1: from X) ----------------
__global__ void prescale_kernel(const float4* __restrict__ src, int srcStride4, int cshift,
                                float4* __restrict__ dst) {
    int idx = blockIdx.x*256 + threadIdx.x;
    int c  = idx & ((1<<cshift)-1);
    int rn = idx >> cshift;
    int n  = rn & (NN-1);
    float  s = g_dv[rn];
    float4 v = src[(size_t)n*srcStride4 + c];
    dst[((size_t)rn<<6) + c] = make_float4(s*v.x, s*v.y, s*v.z, s*v.w);
}

// ---------------- pipelined masked gather-SpMM: mask prefetch depth 2 ----------------
__global__ void __launch_bounds__(512) gather_kernel(
    const unsigned* __restrict__ mask, int Tn, int Sw,
    const float4* __restrict__ src, int relStride4, int srcRowStride4,
    int chunksPerP,
    const float* __restrict__ outScale,
    float4* __restrict__ out)
{
    __shared__ float4 sbuf[4*1024];   // 4 stages x 32 rows x 32 float4 = 64KB

    const int tid  = threadIdx.x, lane = tid & 31, w = tid >> 5;  // 16 warps
    const int tilesT = Tn >> 7;
    const int r  = blockIdx.x / tilesT;
    const int t0 = (blockIdx.x % tilesT) << 7;
    const int p  = blockIdx.z;
    const int colIdx4 = (blockIdx.y << 5) + lane;
    const float4* srcB = src + (size_t)r*relStride4 + (blockIdx.y << 5);
    const int wordBase = p * chunksPerP;
    const int rowBase  = wordBase << 5;
    const unsigned* mbase = mask + ((size_t)(r*Tn + t0 + (w<<3)))*Sw + wordBase;

    auto stage = [&](int c) {
        int st = c & 3;
        int gbase = rowBase + (c << 5);
        #pragma unroll
        for (int k = 0; k < 2; k++) {
            int i = tid + (k << 9);
            int row = i >> 5, col = i & 31;
            __pipeline_memcpy_async(&sbuf[(st<<10) + (row<<5) + col],
                                    srcB + (size_t)(gbase+row)*srcRowStride4 + col, 16);
        }
        __pipeline_commit();
    };

    unsigned long long accA[8], accB[8];
    #pragma unroll
    for (int j = 0; j < 8; j++) { accA[j] = 0ull; accB[j] = 0ull; }

    // mask ring of 2: mreg[c&1] holds chunk c's words
    unsigned mreg[2][8];
    #pragma unroll
    for (int j = 0; j < 8; j++) mreg[0][j] = mbase[(size_t)j*Sw];
    if (chunksPerP > 1) {
        #pragma unroll
        for (int j = 0; j < 8; j++) mreg[1][j] = mbase[(size_t)j*Sw + 1];
    }

    stage(0); stage(1); stage(2);
    for (int c = 0; c < chunksPerP; c++) {
        __pipeline_wait_prior(2);
        __syncthreads();
        if (c + 3 < chunksPerP) stage(c+3);
        else                    __pipeline_commit();
        // prefetch chunk c+2's masks into the slot being freed (c&1)
        unsigned mnxt[8];
        if (c + 2 < chunksPerP) {
            #pragma unroll
            for (int j = 0; j < 8; j++) mnxt[j] = mbase[(size_t)j*Sw + c + 2];
        } else {
            #pragma unroll
            for (int j = 0; j < 8; j++) mnxt[j] = 0u;
        }
        const ulonglong2* bufc = (const ulonglong2*)(sbuf + ((c & 3) << 10));
        #pragma unroll
        for (int j = 0; j < 8; j++) {
            unsigned b = mreg[c & 1][j];
            while (b) {
                int s = __ffs(b) - 1; b &= b - 1;
                ulonglong2 v = bufc[(s << 5) + lane];
                asm("add.rn.f32x2 %0, %0, %1;" : "+l"(accA[j]) : "l"(v.x));
                asm("add.rn.f32x2 %0, %0, %1;" : "+l"(accB[j]) : "l"(v.y));
            }
        }
        #pragma unroll
        for (int j = 0; j < 8; j++) mreg[c & 1][j] = mnxt[j];
    }

    float4* dst = outScale ? out : (g_part + (size_t)p * PART_S4);
    #pragma unroll
    for (int j = 0; j < 8; j++) {
        int t = t0 + (w<<3) + j;
        size_t o = ((size_t)(r*Tn + t) << 6) + colIdx4;
        float4 v = make_float4(
            __uint_as_float((unsigned)(accA[j] & 0xffffffffu)),
            __uint_as_float((unsigned)(accA[j] >> 32)),
            __uint_as_float((unsigned)(accB[j] & 0xffffffffu)),
            __uint_as_float((unsigned)(accB[j] >> 32)));
        if (outScale) {
            float sc = outScale[r*Tn + t];
            v.x *= sc; v.y *= sc; v.z *= sc; v.w *= sc;
        }
        dst[o] = v;
    }
}

// ---------------- combine gather partials ----------------
__global__ void combine_kernel(int P, int nRows, int cshift,
                               const float* __restrict__ scale, float4* __restrict__ out) {
    int idx = blockIdx.x*256 + threadIdx.x;
    int row = idx >> cshift;
    if (row >= nRows) return;
    int c = idx & ((1<<cshift)-1);
    size_t o = ((size_t)row << 6) + c;
    float4 s = g_part[o];
    for (int p = 1; p < P; p++) {
        float4 v = g_part[(size_t)p*PART_S4 + o];
        s.x += v.x; s.y += v.y; s.z += v.z; s.w += v.w;
    }
    float sc = scale[row];
    out[o] = make_float4(sc*s.x, sc*s.y, sc*s.z, sc*s.w);
}

// ---------------- tf32 helpers ----------------
__device__ __forceinline__ unsigned f2tf32(float v) {
    unsigned u;
    asm("cvt.rna.tf32.f32 %0, %1;" : "=r"(u) : "f"(v));
    return u;
}

// ---------------- per-relation projection GEMM: tf32 mma.sync (128x64 tile) ----------------
__global__ void __launch_bounds__(256) gemm_tc_kernel(
    const float* __restrict__ A, int Fin, int Fout,
    const float* __restrict__ W,
    float* __restrict__ part)
{
    __shared__ unsigned sA[32][132];
    __shared__ unsigned sB[32][68];
    const int n0 = blockIdx.x << 7, o0 = blockIdx.y << 6;
    const int rr = blockIdx.z;
    const int tid = threadIdx.x, lane = tid & 31, wid = tid >> 5;
    const int wm = (wid & 3) << 5;
    const int wn = (wid >> 2) << 5;
    const int gid = lane >> 2, tig = lane & 3;

    const float* Ar = A + (size_t)rr*NN*HDIM;
    const float* Wr = W + (size_t)rr*Fin*Fout;

    float c[2][4][4];
    #pragma unroll
    for (int mt = 0; mt < 2; mt++)
        #pragma unroll
        for (int nt = 0; nt < 4; nt++)
            #pragma unroll
            for (int i = 0; i < 4; i++) c[mt][nt][i] = 0.f;

    const int aRow = tid >> 1, aK = (tid & 1) << 4;
    const int bRow = tid >> 3, bN = (tid & 7) << 3;

    for (int k0 = 0; k0 < Fin; k0 += 32) {
        {
            const float* Ap = Ar + (size_t)(n0 + aRow)*HDIM + k0 + aK;
            float4 v0 = *(const float4*)Ap;
            float4 v1 = *(const float4*)(Ap + 4);
            float4 v2 = *(const float4*)(Ap + 8);
            float4 v3 = *(const float4*)(Ap + 12);
            float vv[16] = {v0.x,v0.y,v0.z,v0.w, v1.x,v1.y,v1.z,v1.w,
                            v2.x,v2.y,v2.z,v2.w, v3.x,v3.y,v3.z,v3.w};
            #pragma unroll
            for (int j = 0; j < 16; j++)
                sA[aK + j][aRow] = f2tf32(vv[j]);
        }
        {
            const float* Bp = Wr + (size_t)(k0 + bRow)*Fout + o0 + bN;
            float4 v0 = *(const float4*)Bp;
            float4 v1 = *(const float4*)(Bp + 4);
            float vv[8] = {v0.x,v0.y,v0.z,v0.w, v1.x,v1.y,v1.z,v1.w};
            #pragma unroll
            for (int j = 0; j < 8; j++)
                sB[bRow][bN + j] = f2tf32(vv[j]);
        }
        __syncthreads();

        #pragma unroll
        for (int kk = 0; kk < 32; kk += 8) {
            unsigned a[2][4], b[4][2];
            #pragma unroll
            for (int mt = 0; mt < 2; mt++) {
                int m = wm + (mt << 4);
                a[mt][0] = sA[kk + tig][m + gid];
                a[mt][1] = sA[kk + tig][m + gid + 8];
                a[mt][2] = sA[kk + tig + 4][m + gid];
                a[mt][3] = sA[kk + tig + 4][m + gid + 8];
            }
            #pragma unroll
            for (int nt = 0; nt < 4; nt++) {
                int n = wn + (nt << 3);
                b[nt][0] = sB[kk + tig][n + gid];
                b[nt][1] = sB[kk + tig + 4][n + gid];
            }
            #pragma unroll
            for (int mt = 0; mt < 2; mt++)
                #pragma unroll
                for (int nt = 0; nt < 4; nt++) {
                    asm volatile(
                        "mma.sync.aligned.m16n8k8.row.col.f32.tf32.tf32.f32 "
                        "{%0,%1,%2,%3}, {%4,%5,%6,%7}, {%8,%9}, {%0,%1,%2,%3};"
                        : "+f"(c[mt][nt][0]), "+f"(c[mt][nt][1]),
                          "+f"(c[mt][nt][2]), "+f"(c[mt][nt][3])
                        : "r"(a[mt][0]), "r"(a[mt][1]), "r"(a[mt][2]), "r"(a[mt][3]),
                          "r"(b[nt][0]), "r"(b[nt][1]));
                }
        }
        __syncthreads();
    }

    float* dst = part + (size_t)rr*NN*256;
    #pragma unroll
    for (int mt = 0; mt < 2; mt++) {
        int m = n0 + wm + (mt << 4) + gid;
        #pragma unroll
        for (int nt = 0; nt < 4; nt++) {
            int o = o0 + wn + (nt << 3) + tig*2;
            dst[(size_t)m*Fout + o]       = c[mt][nt][0];
            dst[(size_t)m*Fout + o + 1]   = c[mt][nt][1];
            dst[(size_t)(m+8)*Fout + o]   = c[mt][nt][2];
            dst[(size_t)(m+8)*Fout + o+1] = c[mt][nt][3];
        }
    }
}

// ---------------- fused gemm combine + BN partial stats (Fout = 256 only) ----------------
__global__ void gemm_combine_bn_kernel(const float* __restrict__ part,
                                       const float* __restrict__ sig,
                                       const float* __restrict__ bias,
                                       float4* __restrict__ pre)
{
    const int chunk = blockIdx.x >> 4;
    const int colg  = blockIdx.x & 15;
    const int col4  = colg*4 + (threadIdx.x & 3);
    const int rg    = threadIdx.x >> 2;
    const int n0    = chunk << 8;
    const float s0 = sig[0], s1 = sig[1], s2 = sig[2], s3 = sig[3];
    const float4 b = ((const float4*)bias)[col4];
    const float4* p4 = (const float4*)part;
    float4 S  = make_float4(0.f,0.f,0.f,0.f);
    float4 Q  = make_float4(0.f,0.f,0.f,0.f);
    #pragma unroll
    for (int k = 0; k < 4; k++) {
        int n = n0 + rg + (k << 6);
        size_t o = ((size_t)n << 6) + col4;
        float4 v0 = p4[o];
        float4 v1 = p4[o + (size_t)NN*64];
        float4 v2 = p4[o + (size_t)2*NN*64];
        float4 v3 = p4[o + (size_t)3*NN*64];
        float4 a;
        a.x = b.x + s0*v0.x + s1*v1.x + s2*v2.x + s3*v3.x;
        a.y = b.y + s0*v0.y + s1*v1.y + s2*v2.y + s3*v3.y;
        a.z = b.z + s0*v0.z + s1*v1.z + s2*v2.z + s3*v3.z;
        a.w = b.w + s0*v0.w + s1*v1.w + s2*v2.w + s3*v3.w;
        pre[o] = a;
        S.x += a.x; S.y += a.y; S.z += a.z; S.w += a.w;
        Q.x += a.x*a.x; Q.y += a.y*a.y; Q.z += a.z*a.z; Q.w += a.w*a.w;
    }
    __shared__ float4 sh1[64][4], sh2[64][4];
    sh1[rg][threadIdx.x & 3] = S;
    sh2[rg][threadIdx.x & 3] = Q;
    __syncthreads();
    if (threadIdx.x < 4) {
        float4 SS = make_float4(0.f,0.f,0.f,0.f);
        float4 QQ = make_float4(0.f,0.f,0.f,0.f);
        for (int i = 0; i < 64; i++) {
            float4 a = sh1[i][threadIdx.x], q = sh2[i][threadIdx.x];
            SS.x += a.x; SS.y += a.y; SS.z += a.z; SS.w += a.w;
            QQ.x += q.x; QQ.y += q.y; QQ.z += q.z; QQ.w += q.w;
        }
        int c4 = colg*4 + threadIdx.x;
        ((float4*)&g_bnp[0][chunk][0])[c4] = SS;
        ((float4*)&g_bnp[1][chunk][0])[c4] = QQ;
    }
}

// ---------------- flat gemm combine (final layer, +resid) ----------------
__global__ void gemm_combine_kernel(const float* __restrict__ part, int Fout4,
                                    const float* __restrict__ sig,
                                    const float* __restrict__ bias,
                                    const float* __restrict__ resid,
                                    float* __restrict__ out)
{
    int idx = blockIdx.x*256 + threadIdx.x;
    int o4 = idx % Fout4, n = idx / Fout4;
    float4 s = make_float4(0.f,0.f,0.f,0.f);
    #pragma unroll
    for (int r = 0; r < RR; r++) {
        float sr = sig[r];
        float4 v = *(const float4*)&part[(size_t)r*NN*256 + (size_t)n*(Fout4*4) + o4*4];
        s.x += sr*v.x; s.y += sr*v.y; s.z += sr*v.z; s.w += sr*v.w;
    }
    float4 b = ((const float4*)bias)[o4];
    s.x += b.x; s.y += b.y; s.z += b.z; s.w += b.w;
    if (resid) {
        float4 rv = ((const float4*)resid)[(size_t)n*Fout4 + o4];
        s.x += rv.x; s.y += rv.y; s.z += rv.z; s.w += rv.w;
    }
    ((float4*)out)[(size_t)n*Fout4 + o4] = s;
}

// ---------------- fused BN finalize + apply + LayerNorm + ELU + dv-prescale ----------------
__global__ void bn_ln_elu_scale_kernel(const float* __restrict__ pre,
                                       const float* __restrict__ bg, const float* __restrict__ bb,
                                       const float* __restrict__ lg, const float* __restrict__ lb,
                                       float* __restrict__ xs)
{
    int n = blockIdx.x, c = threadIdx.x;
    // BN finalize (redundant per block; g_bnp is L2-resident)
    float s = 0.f, sq = 0.f;
    #pragma unroll
    for (int k = 0; k < 16; k++) { s += g_bnp[0][k][c]; sq += g_bnp[1][k][c]; }
    float mu  = s * (1.f/(float)NN);
    float var = sq * (1.f/(float)NN) - mu*mu;

    float x = pre[(size_t)n*HDIM + c];
    x = (x - mu) * rsqrtf(var + 1e-5f) * bg[c] + bb[c];
    float s1 = x, s2 = x*x;
    #pragma unroll
    for (int o = 16; o > 0; o >>= 1) {
        s1 += __shfl_xor_sync(0xffffffffu, s1, o);
        s2 += __shfl_xor_sync(0xffffffffu, s2, o);
    }
    __shared__ float a1[8], a2[8];
    if ((c & 31) == 0) { a1[c>>5] = s1; a2[c>>5] = s2; }
    __syncthreads();
    s1 = 0.f; s2 = 0.f;
    #pragma unroll
    for (int k = 0; k < 8; k++) { s1 += a1[k]; s2 += a2[k]; }
    float m = s1 * (1.f/256.f);
    float v = s2 * (1.f/256.f) - m*m;
    x = (x - m) * rsqrtf(v + 1e-5f) * lg[c] + lb[c];
    x = (x > 0.f) ? x : expm1f(x);
    #pragma unroll
    for (int r = 0; r < RR; r++)
        xs[(((size_t)r*NN + n) << 8) + c] = x * g_dv[r*NN + n];
}

// ---------------- launch ----------------
extern "C" void kernel_launch(void* const* d_in, const int* in_sizes, int n_in,
                              void* d_out, int out_size) {
    const float* X    = (const float*)d_in[0];
    const float* H    = (const float*)d_in[1];
    const float* W1   = (const float*)d_in[2];
    const float* W2   = (const float*)d_in[3];
    const float* W3   = (const float*)d_in[4];
    const float* imp  = (const float*)d_in[5];
    const float* b1   = (const float*)d_in[6];
    const float* b2   = (const float*)d_in[7];
    const float* b3   = (const float*)d_in[8];
    const float* bng  = (const float*)d_in[9];
    const float* bnb  = (const float*)d_in[10];
    const float* lng  = (const float*)d_in[11];
    const float* lnb  = (const float*)d_in[12];
    const float* rel  = (const float*)d_in[13];
    float* out = (float*)d_out;

    float *pDv, *pCE, *pSig;
    float4 *pXs, *pT, *pHn, *pPre, *pPart;
    unsigned *pMN, *pME;
    cudaGetSymbolAddress((void**)&pDv, g_dv);
    cudaGetSymbolAddress((void**)&pCE, g_cE);
    cudaGetSymbolAddress((void**)&pSig,g_sig);
    cudaGetSymbolAddress((void**)&pXs, g_Xs);
    cudaGetSymbolAddress((void**)&pT,  g_T);
    cudaGetSymbolAddress((void**)&pHn, g_Hn);
    cudaGetSymbolAddress((void**)&pPre,g_pre);
    cudaGetSymbolAddress((void**)&pPart,g_part);
    cudaGetSymbolAddress((void**)&pMN, g_maskN);
    cudaGetSymbolAddress((void**)&pME, g_maskE);
    float* pGPart = (float*)pPart;

    // ---- structure precompute ----
    prep_kernel<<<1, 32>>>(rel, imp);
    build_maskN_kernel<<<RR*NN/8, 256>>>(H);
    transpose_mask_kernel<<<RR*(NN/32)*(EE/32)/8, 256>>>();
    build_cE_kernel<<<RR*EE/8, 256>>>();

    const int tE = EE/128, tN = NN/128;

    // ---- layer 1 (cols = 128) ----
    prescale_kernel<<<RR*NN*32/256, 256>>>((const float4*)X, 32, 5, pXs);
    gather_kernel<<<dim3(RR*tE, 1, 4), 512>>>(pME, EE, NW, pXs, NN*64, 64, NW/4, nullptr, nullptr);
    combine_kernel<<<RR*EE*32/256, 256>>>(4, RR*EE, 5, pCE, pT);
    gather_kernel<<<dim3(RR*tN, 1, 2), 512>>>(pMN, NN, EW, pT, EE*64, 64, EW/2, nullptr, nullptr);
    combine_kernel<<<RR*NN*32/256, 256>>>(2, RR*NN, 5, pDv, pHn);
    gemm_tc_kernel<<<dim3(NN/128, HDIM/64, RR), 256>>>((const float*)pHn, FF, HDIM, W1, pGPart);
    gemm_combine_bn_kernel<<<256, 256>>>(pGPart, pSig + 0*RR, b1, pPre);
    bn_ln_elu_scale_kernel<<<NN, HDIM>>>((const float*)pPre, bng, bnb, lng, lnb, (float*)pXs);

    // ---- layer 2 (cols = 256) ----
    gather_kernel<<<dim3(RR*tE, 2, 2), 512>>>(pME, EE, NW, pXs, NN*64, 64, NW/2, nullptr, nullptr);
    combine_kernel<<<RR*EE*64/256, 256>>>(2, RR*EE, 6, pCE, pT);
    gather_kernel<<<dim3(RR*tN, 2, 1), 512>>>(pMN, NN, EW, pT, EE*64, 64, EW, pDv, pHn);
    gemm_tc_kernel<<<dim3(NN/128, HDIM/64, RR), 256>>>((const float*)pHn, HDIM, HDIM, W2, pGPart);
    gemm_combine_bn_kernel<<<256, 256>>>(pGPart, pSig + 1*RR, b2, pPre);
    bn_ln_elu_scale_kernel<<<NN, HDIM>>>((const float*)pPre, bng + HDIM, bnb + HDIM, lng + HDIM, lnb + HDIM, (float*)pXs);

    // ---- layer 3 (cols = 256) + residual ----
    gather_kernel<<<dim3(RR*tE, 2, 2), 512>>>(pME, EE, NW, pXs, NN*64, 64, NW/2, nullptr, nullptr);
    combine_kernel<<<RR*EE*64/256, 256>>>(2, RR*EE, 6, pCE, pT);
    gather_kernel<<<dim3(RR*tN, 2, 1), 512>>>(pMN, NN, EW, pT, EE*64, 64, EW, pDv, pHn);
    gemm_tc_kernel<<<dim3(NN/128, FF/64, RR), 256>>>((const float*)pHn, HDIM, FF, W3, pGPart);
    gemm_combine_kernel<<<NN*(FF/4)/256, 256>>>(pGPart, FF/4, pSig + 2*RR, b3, X, out);
}

// round 15
// speedup vs baseline: 1.3589x; 1.3589x over previous
#include <cuda_runtime.h>
#include <cuda_pipeline.h>
#include <math.h>

#define RR 4
#define NN 4096
#define EE 2048
#define FF 128
#define HDIM 256
#define EW (EE/32)
#define NW (NN/32)
#define PART_S4 (RR*NN*64)

// ---------------- device scratch ----------------
__device__ float    g_rw[RR];
__device__ float    g_sig[3][RR];
__device__ float    g_dv[RR*NN];
__device__ float    g_cE[RR*EE];
__device__ unsigned g_maskN[(size_t)RR*NN*EW];
__device__ unsigned g_maskE[(size_t)RR*EE*NW];
__device__ float4   g_Xs [(size_t)RR*NN*64];
__device__ float4   g_T  [(size_t)RR*EE*64];
__device__ float4   g_Hn [(size_t)RR*NN*64];
__device__ float4   g_pre[(size_t)NN*64];
__device__ float4   g_part[(size_t)4*PART_S4];
__device__ float    g_mu[HDIM], g_var[HDIM];
__device__ float    g_bnp[2][16][HDIM];

// ---------------- prep ----------------
__global__ void prep_kernel(const float* __restrict__ rel, const float* __restrict__ imp) {
    if (threadIdx.x == 0) {
        float m = -1e30f;
        for (int r = 0; r < RR; r++) m = fmaxf(m, rel[r]);
        float e[RR], s = 0.f;
        for (int r = 0; r < RR; r++) { e[r] = expf(rel[r] - m); s += e[r]; }
        for (int r = 0; r < RR; r++) g_rw[r] = e[r] / s;
        for (int l = 0; l < 3; l++)
            for (int r = 0; r < RR; r++)
                g_sig[l][r] = 1.f / (1.f + expf(-imp[l*RR + r]));
    }
}

// ---------------- bitmask build ----------------
__global__ void build_maskN_kernel(const float* __restrict__ H) {
    int gw   = blockIdx.x * (blockDim.x >> 5) + (threadIdx.x >> 5);
    int lane = threadIdx.x & 31;
    if (gw >= RR*NN) return;
    int r = gw / NN;
    const float* row = H + (size_t)gw * EE;
    unsigned w0 = 0, w1 = 0;
    int cnt = 0;
    #pragma unroll 8
    for (int k = 0; k < 64; k++) {
        float v = row[k*32 + lane];
        unsigned b = __ballot_sync(0xffffffffu, v != 0.0f);
        cnt += (v != 0.0f) ? 1 : 0;
        if (k == lane)      w0 = b;
        if (k == lane + 32) w1 = b;
    }
    g_maskN[(size_t)gw*EW + lane]      = w0;
    g_maskN[(size_t)gw*EW + 32 + lane] = w1;
    int tot = __reduce_add_sync(0xffffffffu, cnt);
    if (lane == 0)
        g_dv[gw] = 1.0f / sqrtf(g_rw[r] * (float)tot + 1e-8f);
}

// ---------------- 32x32 bit transpose ----------------
__global__ void transpose_mask_kernel() {
    const int tilesPerR = (NN/32)*(EE/32);
    int gw   = blockIdx.x * (blockDim.x >> 5) + (threadIdx.x >> 5);
    int lane = threadIdx.x & 31;
    if (gw >= RR * tilesPerR) return;
    int r   = gw / tilesPerR;
    int rem = gw % tilesPerR;
    int nb  = rem / (EE/32);
    int eb  = rem % (EE/32);
    unsigned w = g_maskN[((size_t)r*NN + nb*32 + lane)*EW + eb];
    unsigned out = 0;
    #pragma unroll
    for (int j = 0; j < 32; j++) {
        unsigned b = __ballot_sync(0xffffffffu, (w >> j) & 1u);
        if (lane == j) out = b;
    }
    g_maskE[((size_t)r*EE + eb*32 + lane)*NW + nb] = out;
}

// ---------------- edge constants ----------------
__global__ void build_cE_kernel() {
    int gw   = blockIdx.x * (blockDim.x >> 5) + (threadIdx.x >> 5);
    int lane = threadIdx.x & 31;
    if (gw >= RR*EE) return;
    int r = gw / EE;
    const unsigned* row = g_maskE + (size_t)gw * NW;
    int cnt = 0;
    for (int k = lane; k < NW; k += 32) cnt += __popc(row[k]);
    cnt = __reduce_add_sync(0xffffffffu, cnt);
    if (lane == 0) {
        float rw = g_rw[r];
        g_cE[gw] = rw * rw / (rw * (float)cnt + 1e-8f);
    }
}

// ---------------- pre-scale source by dv (layer 1: from X) ----------------
__global__ void prescale_kernel(const float4* __restrict__ src, int srcStride4, int cshift,
                                float4* __restrict__ dst) {
    int idx = blockIdx.x*256 + threadIdx.x;
    int c  = idx & ((1<<cshift)-1);
    int rn = idx >> cshift;
    int n  = rn & (NN-1);
    float  s = g_dv[rn];
    float4 v = src[(size_t)n*srcStride4 + c];
    dst[((size_t)rn<<6) + c] = make_float4(s*v.x, s*v.y, s*v.z, s*v.w);
}

// ---------------- pipelined masked gather-SpMM: 512 thr, mask register double-buffer ----------------
__global__ void __launch_bounds__(512) gather_kernel(
    const unsigned* __restrict__ mask, int Tn, int Sw,
    const float4* __restrict__ src, int relStride4, int srcRowStride4,
    int chunksPerP,
    const float* __restrict__ outScale,
    float4* __restrict__ out)
{
    __shared__ float4 sbuf[4*1024];   // 4 stages x 32 rows x 32 float4 = 64KB

    const int tid  = threadIdx.x, lane = tid & 31, w = tid >> 5;  // 16 warps
    const int tilesT = Tn >> 7;
    const int r  = blockIdx.x / tilesT;
    const int t0 = (blockIdx.x % tilesT) << 7;
    const int p  = blockIdx.z;
    const int colIdx4 = (blockIdx.y << 5) + lane;
    const float4* srcB = src + (size_t)r*relStride4 + (blockIdx.y << 5);
    const int wordBase = p * chunksPerP;
    const int rowBase  = wordBase << 5;
    const unsigned* mbase = mask + ((size_t)(r*Tn + t0 + (w<<3)))*Sw + wordBase;

    auto stage = [&](int c) {
        int st = c & 3;
        int gbase = rowBase + (c << 5);
        #pragma unroll
        for (int k = 0; k < 2; k++) {
            int i = tid + (k << 9);
            int row = i >> 5, col = i & 31;
            __pipeline_memcpy_async(&sbuf[(st<<10) + (row<<5) + col],
                                    srcB + (size_t)(gbase+row)*srcRowStride4 + col, 16);
        }
        __pipeline_commit();
    };

    unsigned long long accA[8], accB[8];
    #pragma unroll
    for (int j = 0; j < 8; j++) { accA[j] = 0ull; accB[j] = 0ull; }

    // mask register double-buffer: cur = chunk c words, prefetched one chunk ahead
    unsigned mcur[8];
    #pragma unroll
    for (int j = 0; j < 8; j++) mcur[j] = mbase[(size_t)j*Sw];

    stage(0); stage(1); stage(2);
    for (int c = 0; c < chunksPerP; c++) {
        __pipeline_wait_prior(2);
        __syncthreads();
        if (c + 3 < chunksPerP) stage(c+3);
        else                    __pipeline_commit();
        // prefetch next chunk's masks (latency hidden behind this chunk's walk)
        unsigned mnxt[8];
        if (c + 1 < chunksPerP) {
            #pragma unroll
            for (int j = 0; j < 8; j++) mnxt[j] = mbase[(size_t)j*Sw + c + 1];
        } else {
            #pragma unroll
            for (int j = 0; j < 8; j++) mnxt[j] = 0u;
        }
        const ulonglong2* bufc = (const ulonglong2*)(sbuf + ((c & 3) << 10));
        #pragma unroll
        for (int j = 0; j < 8; j++) {
            unsigned b = mcur[j];
            while (b) {
                int s = __ffs(b) - 1; b &= b - 1;
                ulonglong2 v = bufc[(s << 5) + lane];
                asm("add.rn.f32x2 %0, %0, %1;" : "+l"(accA[j]) : "l"(v.x));
                asm("add.rn.f32x2 %0, %0, %1;" : "+l"(accB[j]) : "l"(v.y));
            }
        }
        #pragma unroll
        for (int j = 0; j < 8; j++) mcur[j] = mnxt[j];
    }

    float4* dst = outScale ? out : (g_part + (size_t)p * PART_S4);
    #pragma unroll
    for (int j = 0; j < 8; j++) {
        int t = t0 + (w<<3) + j;
        size_t o = ((size_t)(r*Tn + t) << 6) + colIdx4;
        float4 v = make_float4(
            __uint_as_float((unsigned)(accA[j] & 0xffffffffu)),
            __uint_as_float((unsigned)(accA[j] >> 32)),
            __uint_as_float((unsigned)(accB[j] & 0xffffffffu)),
            __uint_as_float((unsigned)(accB[j] >> 32)));
        if (outScale) {
            float sc = outScale[r*Tn + t];
            v.x *= sc; v.y *= sc; v.z *= sc; v.w *= sc;
        }
        dst[o] = v;
    }
}

// ---------------- combine gather partials ----------------
__global__ void combine_kernel(int P, int nRows, int cshift,
                               const float* __restrict__ scale, float4* __restrict__ out) {
    int idx = blockIdx.x*256 + threadIdx.x;
    int row = idx >> cshift;
    if (row >= nRows) return;
    int c = idx & ((1<<cshift)-1);
    size_t o = ((size_t)row << 6) + c;
    float4 s = g_part[o];
    for (int p = 1; p < P; p++) {
        float4 v = g_part[(size_t)p*PART_S4 + o];
        s.x += v.x; s.y += v.y; s.z += v.z; s.w += v.w;
    }
    float sc = scale[row];
    out[o] = make_float4(sc*s.x, sc*s.y, sc*s.z, sc*s.w);
}

// ---------------- tf32 helpers ----------------
__device__ __forceinline__ unsigned f2tf32(float v) {
    unsigned u;
    asm("cvt.rna.tf32.f32 %0, %1;" : "=r"(u) : "f"(v));
    return u;
}

// ---------------- per-relation projection GEMM: tf32 mma.sync (128x64 tile) ----------------
__global__ void __launch_bounds__(256) gemm_tc_kernel(
    const float* __restrict__ A, int Fin, int Fout,
    const float* __restrict__ W,
    float* __restrict__ part)
{
    __shared__ unsigned sA[32][132];
    __shared__ unsigned sB[32][68];
    const int n0 = blockIdx.x << 7, o0 = blockIdx.y << 6;
    const int rr = blockIdx.z;
    const int tid = threadIdx.x, lane = tid & 31, wid = tid >> 5;
    const int wm = (wid & 3) << 5;
    const int wn = (wid >> 2) << 5;
    const int gid = lane >> 2, tig = lane & 3;

    const float* Ar = A + (size_t)rr*NN*HDIM;
    const float* Wr = W + (size_t)rr*Fin*Fout;

    float c[2][4][4];
    #pragma unroll
    for (int mt = 0; mt < 2; mt++)
        #pragma unroll
        for (int nt = 0; nt < 4; nt++)
            #pragma unroll
            for (int i = 0; i < 4; i++) c[mt][nt][i] = 0.f;

    const int aRow = tid >> 1, aK = (tid & 1) << 4;
    const int bRow = tid >> 3, bN = (tid & 7) << 3;

    for (int k0 = 0; k0 < Fin; k0 += 32) {
        {
            const float* Ap = Ar + (size_t)(n0 + aRow)*HDIM + k0 + aK;
            float4 v0 = *(const float4*)Ap;
            float4 v1 = *(const float4*)(Ap + 4);
            float4 v2 = *(const float4*)(Ap + 8);
            float4 v3 = *(const float4*)(Ap + 12);
            float vv[16] = {v0.x,v0.y,v0.z,v0.w, v1.x,v1.y,v1.z,v1.w,
                            v2.x,v2.y,v2.z,v2.w, v3.x,v3.y,v3.z,v3.w};
            #pragma unroll
            for (int j = 0; j < 16; j++)
                sA[aK + j][aRow] = f2tf32(vv[j]);
        }
        {
            const float* Bp = Wr + (size_t)(k0 + bRow)*Fout + o0 + bN;
            float4 v0 = *(const float4*)Bp;
            float4 v1 = *(const float4*)(Bp + 4);
            float vv[8] = {v0.x,v0.y,v0.z,v0.w, v1.x,v1.y,v1.z,v1.w};
            #pragma unroll
            for (int j = 0; j < 8; j++)
                sB[bRow][bN + j] = f2tf32(vv[j]);
        }
        __syncthreads();

        #pragma unroll
        for (int kk = 0; kk < 32; kk += 8) {
            unsigned a[2][4], b[4][2];
            #pragma unroll
            for (int mt = 0; mt < 2; mt++) {
                int m = wm + (mt << 4);
                a[mt][0] = sA[kk + tig][m + gid];
                a[mt][1] = sA[kk + tig][m + gid + 8];
                a[mt][2] = sA[kk + tig + 4][m + gid];
                a[mt][3] = sA[kk + tig + 4][m + gid + 8];
            }
            #pragma unroll
            for (int nt = 0; nt < 4; nt++) {
                int n = wn + (nt << 3);
                b[nt][0] = sB[kk + tig][n + gid];
                b[nt][1] = sB[kk + tig + 4][n + gid];
            }
            #pragma unroll
            for (int mt = 0; mt < 2; mt++)
                #pragma unroll
                for (int nt = 0; nt < 4; nt++) {
                    asm volatile(
                        "mma.sync.aligned.m16n8k8.row.col.f32.tf32.tf32.f32 "
                        "{%0,%1,%2,%3}, {%4,%5,%6,%7}, {%8,%9}, {%0,%1,%2,%3};"
                        : "+f"(c[mt][nt][0]), "+f"(c[mt][nt][1]),
                          "+f"(c[mt][nt][2]), "+f"(c[mt][nt][3])
                        : "r"(a[mt][0]), "r"(a[mt][1]), "r"(a[mt][2]), "r"(a[mt][3]),
                          "r"(b[nt][0]), "r"(b[nt][1]));
                }
        }
        __syncthreads();
    }

    float* dst = part + (size_t)rr*NN*256;
    #pragma unroll
    for (int mt = 0; mt < 2; mt++) {
        int m = n0 + wm + (mt << 4) + gid;
        #pragma unroll
        for (int nt = 0; nt < 4; nt++) {
            int o = o0 + wn + (nt << 3) + tig*2;
            dst[(size_t)m*Fout + o]       = c[mt][nt][0];
            dst[(size_t)m*Fout + o + 1]   = c[mt][nt][1];
            dst[(size_t)(m+8)*Fout + o]   = c[mt][nt][2];
            dst[(size_t)(m+8)*Fout + o+1] = c[mt][nt][3];
        }
    }
}

// ---------------- fused gemm combine + BN partial stats (Fout = 256 only) ----------------
__global__ void gemm_combine_bn_kernel(const float* __restrict__ part,
                                       const float* __restrict__ sig,
                                       const float* __restrict__ bias,
                                       float4* __restrict__ pre)
{
    const int chunk = blockIdx.x >> 4;
    const int colg  = blockIdx.x & 15;
    const int col4  = colg*4 + (threadIdx.x & 3);
    const int rg    = threadIdx.x >> 2;
    const int n0    = chunk << 8;
    const float s0 = sig[0], s1 = sig[1], s2 = sig[2], s3 = sig[3];
    const float4 b = ((const float4*)bias)[col4];
    const float4* p4 = (const float4*)part;
    float4 S  = make_float4(0.f,0.f,0.f,0.f);
    float4 Q  = make_float4(0.f,0.f,0.f,0.f);
    #pragma unroll
    for (int k = 0; k < 4; k++) {
        int n = n0 + rg + (k << 6);
        size_t o = ((size_t)n << 6) + col4;
        float4 v0 = p4[o];
        float4 v1 = p4[o + (size_t)NN*64];
        float4 v2 = p4[o + (size_t)2*NN*64];
        float4 v3 = p4[o + (size_t)3*NN*64];
        float4 a;
        a.x = b.x + s0*v0.x + s1*v1.x + s2*v2.x + s3*v3.x;
        a.y = b.y + s0*v0.y + s1*v1.y + s2*v2.y + s3*v3.y;
        a.z = b.z + s0*v0.z + s1*v1.z + s2*v2.z + s3*v3.z;
        a.w = b.w + s0*v0.w + s1*v1.w + s2*v2.w + s3*v3.w;
        pre[o] = a;
        S.x += a.x; S.y += a.y; S.z += a.z; S.w += a.w;
        Q.x += a.x*a.x; Q.y += a.y*a.y; Q.z += a.z*a.z; Q.w += a.w*a.w;
    }
    __shared__ float4 sh1[64][4], sh2[64][4];
    sh1[rg][threadIdx.x & 3] = S;
    sh2[rg][threadIdx.x & 3] = Q;
    __syncthreads();
    if (threadIdx.x < 4) {
        float4 SS = make_float4(0.f,0.f,0.f,0.f);
        float4 QQ = make_float4(0.f,0.f,0.f,0.f);
        for (int i = 0; i < 64; i++) {
            float4 a = sh1[i][threadIdx.x], q = sh2[i][threadIdx.x];
            SS.x += a.x; SS.y += a.y; SS.z += a.z; SS.w += a.w;
            QQ.x += q.x; QQ.y += q.y; QQ.z += q.z; QQ.w += q.w;
        }
        int c4 = colg*4 + threadIdx.x;
        ((float4*)&g_bnp[0][chunk][0])[c4] = SS;
        ((float4*)&g_bnp[1][chunk][0])[c4] = QQ;
    }
}

// ---------------- flat gemm combine (final layer, +resid) ----------------
__global__ void gemm_combine_kernel(const float* __restrict__ part, int Fout4,
                                    const float* __restrict__ sig,
                                    const float* __restrict__ bias,
                                    const float* __restrict__ resid,
                                    float* __restrict__ out)
{
    int idx = blockIdx.x*256 + threadIdx.x;
    int o4 = idx % Fout4, n = idx / Fout4;
    float4 s = make_float4(0.f,0.f,0.f,0.f);
    #pragma unroll
    for (int r = 0; r < RR; r++) {
        float sr = sig[r];
        float4 v = *(const float4*)&part[(size_t)r*NN*256 + (size_t)n*(Fout4*4) + o4*4];
        s.x += sr*v.x; s.y += sr*v.y; s.z += sr*v.z; s.w += sr*v.w;
    }
    float4 b = ((const float4*)bias)[o4];
    s.x += b.x; s.y += b.y; s.z += b.z; s.w += b.w;
    if (resid) {
        float4 rv = ((const float4*)resid)[(size_t)n*Fout4 + o4];
        s.x += rv.x; s.y += rv.y; s.z += rv.z; s.w += rv.w;
    }
    ((float4*)out)[(size_t)n*Fout4 + o4] = s;
}

// ---------------- BN stats finalize ----------------
__global__ void bn_stats2_kernel() {
    int c = threadIdx.x;
    float s = 0.f, sq = 0.f;
    #pragma unroll
    for (int k = 0; k < 16; k++) { s += g_bnp[0][k][c]; sq += g_bnp[1][k][c]; }
    float mu = s / (float)NN;
    g_mu[c]  = mu;
    g_var[c] = sq / (float)NN - mu*mu;
}

// ---------------- fused BN apply + LayerNorm + ELU + dv-prescale ----------------
__global__ void bn_ln_elu_scale_kernel(const float* __restrict__ pre,
                                       const float* __restrict__ bg, const float* __restrict__ bb,
                                       const float* __restrict__ lg, const float* __restrict__ lb,
                                       float* __restrict__ xs)
{
    int n = blockIdx.x, c = threadIdx.x;
    float x = pre[(size_t)n*HDIM + c];
    x = (x - g_mu[c]) * rsqrtf(g_var[c] + 1e-5f) * bg[c] + bb[c];
    float s1 = x, s2 = x*x;
    #pragma unroll
    for (int o = 16; o > 0; o >>= 1) {
        s1 += __shfl_xor_sync(0xffffffffu, s1, o);
        s2 += __shfl_xor_sync(0xffffffffu, s2, o);
    }
    __shared__ float a1[8], a2[8];
    if ((c & 31) == 0) { a1[c>>5] = s1; a2[c>>5] = s2; }
    __syncthreads();
    s1 = 0.f; s2 = 0.f;
    #pragma unroll
    for (int k = 0; k < 8; k++) { s1 += a1[k]; s2 += a2[k]; }
    float m = s1 * (1.f/256.f);
    float v = s2 * (1.f/256.f) - m*m;
    x = (x - m) * rsqrtf(v + 1e-5f) * lg[c] + lb[c];
    x = (x > 0.f) ? x : expm1f(x);
    #pragma unroll
    for (int r = 0; r < RR; r++)
        xs[(((size_t)r*NN + n) << 8) + c] = x * g_dv[r*NN + n];
}

// ---------------- launch ----------------
extern "C" void kernel_launch(void* const* d_in, const int* in_sizes, int n_in,
                              void* d_out, int out_size) {
    const float* X    = (const float*)d_in[0];
    const float* H    = (const float*)d_in[1];
    const float* W1   = (const float*)d_in[2];
    const float* W2   = (const float*)d_in[3];
    const float* W3   = (const float*)d_in[4];
    const float* imp  = (const float*)d_in[5];
    const float* b1   = (const float*)d_in[6];
    const float* b2   = (const float*)d_in[7];
    const float* b3   = (const float*)d_in[8];
    const float* bng  = (const float*)d_in[9];
    const float* bnb  = (const float*)d_in[10];
    const float* lng  = (const float*)d_in[11];
    const float* lnb  = (const float*)d_in[12];
    const float* rel  = (const float*)d_in[13];
    float* out = (float*)d_out;

    float *pDv, *pCE, *pSig;
    float4 *pXs, *pT, *pHn, *pPre, *pPart;
    unsigned *pMN, *pME;
    cudaGetSymbolAddress((void**)&pDv, g_dv);
    cudaGetSymbolAddress((void**)&pCE, g_cE);
    cudaGetSymbolAddress((void**)&pSig,g_sig);
    cudaGetSymbolAddress((void**)&pXs, g_Xs);
    cudaGetSymbolAddress((void**)&pT,  g_T);
    cudaGetSymbolAddress((void**)&pHn, g_Hn);
    cudaGetSymbolAddress((void**)&pPre,g_pre);
    cudaGetSymbolAddress((void**)&pPart,g_part);
    cudaGetSymbolAddress((void**)&pMN, g_maskN);
    cudaGetSymbolAddress((void**)&pME, g_maskE);
    float* pGPart = (float*)pPart;

    // ---- structure precompute ----
    prep_kernel<<<1, 32>>>(rel, imp);
    build_maskN_kernel<<<RR*NN/8, 256>>>(H);
    transpose_mask_kernel<<<RR*(NN/32)*(EE/32)/8, 256>>>();
    build_cE_kernel<<<RR*EE/8, 256>>>();

    const int tE = EE/128, tN = NN/128;

    // ---- layer 1 (cols = 128) ----
    prescale_kernel<<<RR*NN*32/256, 256>>>((const float4*)X, 32, 5, pXs);
    gather_kernel<<<dim3(RR*tE, 1, 4), 512>>>(pME, EE, NW, pXs, NN*64, 64, NW/4, nullptr, nullptr);
    combine_kernel<<<RR*EE*32/256, 256>>>(4, RR*EE, 5, pCE, pT);
    gather_kernel<<<dim3(RR*tN, 1, 2), 512>>>(pMN, NN, EW, pT, EE*64, 64, EW/2, nullptr, nullptr);
    combine_kernel<<<RR*NN*32/256, 256>>>(2, RR*NN, 5, pDv, pHn);
    gemm_tc_kernel<<<dim3(NN/128, HDIM/64, RR), 256>>>((const float*)pHn, FF, HDIM, W1, pGPart);
    gemm_combine_bn_kernel<<<256, 256>>>(pGPart, pSig + 0*RR, b1, pPre);
    bn_stats2_kernel<<<1, HDIM>>>();
    bn_ln_elu_scale_kernel<<<NN, HDIM>>>((const float*)pPre, bng, bnb, lng, lnb, (float*)pXs);

    // ---- layer 2 (cols = 256) ----
    gather_kernel<<<dim3(RR*tE, 2, 2), 512>>>(pME, EE, NW, pXs, NN*64, 64, NW/2, nullptr, nullptr);
    combine_kernel<<<RR*EE*64/256, 256>>>(2, RR*EE, 6, pCE, pT);
    gather_kernel<<<dim3(RR*tN, 2, 1), 512>>>(pMN, NN, EW, pT, EE*64, 64, EW, pDv, pHn);
    gemm_tc_kernel<<<dim3(NN/128, HDIM/64, RR), 256>>>((const float*)pHn, HDIM, HDIM, W2, pGPart);
    gemm_combine_bn_kernel<<<256, 256>>>(pGPart, pSig + 1*RR, b2, pPre);
    bn_stats2_kernel<<<1, HDIM>>>();
    bn_ln_elu_scale_kernel<<<NN, HDIM>>>((const float*)pPre, bng + HDIM, bnb + HDIM, lng + HDIM, lnb + HDIM, (float*)pXs);

    // ---- layer 3 (cols = 256) + residual ----
    gather_kernel<<<dim3(RR*tE, 2, 2), 512>>>(pME, EE, NW, pXs, NN*64, 64, NW/2, nullptr, nullptr);
    combine_kernel<<<RR*EE*64/256, 256>>>(2, RR*EE, 6, pCE, pT);
    gather_kernel<<<dim3(RR*tN, 2, 1), 512>>>(pMN, NN, EW, pT, EE*64, 64, EW, pDv, pHn);
    gemm_tc_kernel<<<dim3(NN/128, FF/64, RR), 256>>>((const float*)pHn, HDIM, FF, W3, pGPart);
    gemm_combine_kernel<<<NN*(FF/4)/256, 256>>>(pGPart, FF/4, pSig + 2*RR, b3, X, out);
}